// round 16
// baseline (speedup 1.0000x reference)
#include <cuda_runtime.h>
#include <cuda_fp16.h>
#include <cstdint>

#define Bsz     32768
#define Dd      1024
#define Cc      40
#define CT      80            // 40 fwd + 40 rev output columns
#define RB      128           // rows (M) per CTA -> 256 CTAs
#define THREADS 512           // 16 warps: 8 M-warps x 2 N-warps, each 1 m-tile x 5 n-tiles
#define KC      32            // k per chunk
#define NCH     (Dd / KC)     // 32
#define NST     4             // ring depth

#define PADK    40                        // A fp32 floats/row (160B): (4qr+qc)%16 all-distinct
#define A_STAGE_B (RB * PADK * 4)         // 20480
#define AROWB   80                        // B fp16 row bytes - LDSM conflict-free
#define B_STAGE_B (CT * AROWB)            // 6400
#define OFF_A0  1024
#define OFF_B0  (OFF_A0 + NST * A_STAGE_B)     // 82944
#define SMEM_BYTES (OFF_B0 + NST * B_STAGE_B)  // 108544 -> 2 CTAs/SM (217KB/228KB)

// epilogue overlay (aliases rings after mainloop)
#define BROW    81
#define EPI_BASE_F 256
#define EPI_WT_F   (EPI_BASE_F + RB * BROW)
#define EPI_BB_F   (EPI_WT_F + 2 * Cc * Cc)

__device__ __half Wh[CT * Dd];   // fp16 copy of GEMM part of [W;W_rev]

extern __shared__ float smf[];

__device__ __forceinline__ uint32_t pk(float lo, float hi) {
    uint32_t r;
    asm("cvt.rn.f16x2.f32 %0, %1, %2;" : "=r"(r) : "f"(hi), "f"(lo));
    return r;
}

__device__ __forceinline__ void mma_16x8x16(float* d, const uint32_t* a,
                                            const uint32_t* bf) {
    asm volatile(
        "mma.sync.aligned.m16n8k16.row.col.f32.f16.f16.f32 "
        "{%0,%1,%2,%3}, {%4,%5,%6,%7}, {%8,%9}, {%0,%1,%2,%3};"
        : "+f"(d[0]), "+f"(d[1]), "+f"(d[2]), "+f"(d[3])
        : "r"(a[0]), "r"(a[1]), "r"(a[2]), "r"(a[3]), "r"(bf[0]), "r"(bf[1]));
}

__device__ __forceinline__ void ldsm4(uint32_t* r, uint32_t a) {
    asm volatile("ldmatrix.sync.aligned.m8n8.x4.shared.b16 {%0,%1,%2,%3}, [%4];"
                 : "=r"(r[0]), "=r"(r[1]), "=r"(r[2]), "=r"(r[3]) : "r"(a));
}
__device__ __forceinline__ void ldsm2(uint32_t* r, uint32_t a) {
    asm volatile("ldmatrix.sync.aligned.m8n8.x2.shared.b16 {%0,%1}, [%2];"
                 : "=r"(r[0]), "=r"(r[1]) : "r"(a));
}

__global__ void convert_w(const float* __restrict__ W,
                          const float* __restrict__ Wr) {
    const int idx = blockIdx.x * 256 + threadIdx.x;
    if (idx < CT * Dd) {
        const int r = idx >> 10, k = idx & 1023;
        const float* Wp = (r < Cc) ? W  + (size_t)r        * (Dd + Cc)
                                   : Wr + (size_t)(r - Cc) * (Dd + Cc);
        Wh[idx] = __float2half_rn(Wp[k]);
    }
}

__global__ void __launch_bounds__(THREADS, 2)
bichain_w16(const float* __restrict__ src,
            const float* __restrict__ W,  const float* __restrict__ b,
            const float* __restrict__ Wr, const float* __restrict__ br,
            float* __restrict__ out) {
    const int tid  = threadIdx.x;
    const int warp = tid >> 5;
    const int lane = tid & 31;
    const int row0 = blockIdx.x * RB;

    uint32_t smb;
    asm("{ .reg .u64 t; cvta.to.shared.u64 t, %1; cvt.u32.u64 %0, t; }"
        : "=r"(smb) : "l"(smf));

    // ---- producer mapping: A 1024x16B over 512 thr (2 each); B 320x16B (tid<320) ----
    const int arow = tid >> 3, aseg = tid & 7;           // arow 0..63
    const float* gA0 = src + (size_t)(row0 + arow) * Dd + aseg * 4;
    const float* gA1 = src + (size_t)(row0 + arow + 64) * Dd + aseg * 4;
    const uint32_t dA0 = (uint32_t)(arow * (PADK * 4) + aseg * 16);
    const uint32_t dA1 = (uint32_t)((arow + 64) * (PADK * 4) + aseg * 16);
    const int brow = tid >> 2, bseg = tid & 3;           // valid when tid<320
    const __half* gB0 = Wh + (size_t)(brow < CT ? brow : 0) * Dd + bseg * 8;
    const uint32_t dB0 = (uint32_t)((brow < CT ? brow : 0) * AROWB + bseg * 16);

    auto issue = [&](int ch) {
        if (ch < NCH) {
            const uint32_t aS = smb + OFF_A0 + (uint32_t)(ch & 3) * A_STAGE_B;
            const uint32_t bS = smb + OFF_B0 + (uint32_t)(ch & 3) * B_STAGE_B;
            const int k0 = ch * KC;
            asm volatile("cp.async.cg.shared.global [%0], [%1], 16;"
                         :: "r"(aS + dA0), "l"(gA0 + k0));
            asm volatile("cp.async.cg.shared.global [%0], [%1], 16;"
                         :: "r"(aS + dA1), "l"(gA1 + k0));
            if (tid < CT * 4)
                asm volatile("cp.async.ca.shared.global [%0], [%1], 16;"
                             :: "r"(bS + dB0), "l"(gB0 + k0));
        }
        asm volatile("cp.async.commit_group;");   // uniform accounting
    };

    // ---- consumer offsets: 8 M-warps x 2 N-warps, 1 m-tile x 5 n-tiles ----
    const int mw = warp >> 1, nw = warp & 1;     // mw 0..7
    const int qr = lane >> 2, qc = lane & 3;
    const int g8 = lane >> 3, i8 = lane & 7;

    int rA2[2];                                   // A float2 indices (rows r, r+8)
    {
        const int r = mw * 16 + qr;
        rA2[0] = r * (PADK / 2) + qc;
        rA2[1] = (r + 8) * (PADK / 2) + qc;
    }
    uint32_t boff[2][2], boffc[2];
    #pragma unroll
    for (int p = 0; p < 2; ++p)
        #pragma unroll
        for (int kk = 0; kk < 2; ++kk)
            boff[p][kk] = (uint32_t)((nw * 40 + p * 16 + (g8 >> 1) * 8 + i8) * AROWB
                                     + (g8 & 1) * 16 + kk * 32);
    {
        const int l2g = (lane & 15) >> 3;
        #pragma unroll
        for (int kk = 0; kk < 2; ++kk)
            boffc[kk] = (uint32_t)((nw * 40 + 32 + i8) * AROWB + l2g * 16 + kk * 32);
    }

    float acc[5][4];
    #pragma unroll
    for (int t = 0; t < 5; ++t)
        #pragma unroll
        for (int e = 0; e < 4; ++e) acc[t][e] = 0.f;

    // ---- prologue: 3 chunks in flight ----
    issue(0); issue(1); issue(2);

    for (int ch = 0; ch < NCH; ++ch) {
        asm volatile("cp.async.wait_group 2;");
        __syncthreads();
        issue(ch + 3);

        const float2* Ap2 =
            (const float2*)((const char*)smf + OFF_A0 + (ch & 3) * A_STAGE_B);
        const uint32_t sbB = smb + OFF_B0 + (uint32_t)(ch & 3) * B_STAGE_B;

        #pragma unroll
        for (int kk = 0; kk < 2; ++kk) {
            const int kb2 = kk * 8;
            uint32_t afr[4], q0[4], q1[4], q2[2];
            {
                float2 p0 = Ap2[rA2[0] + kb2];
                float2 p1 = Ap2[rA2[1] + kb2];
                float2 p2 = Ap2[rA2[0] + kb2 + 4];
                float2 p3 = Ap2[rA2[1] + kb2 + 4];
                afr[0] = pk(p0.x, p0.y);
                afr[1] = pk(p1.x, p1.y);
                afr[2] = pk(p2.x, p2.y);
                afr[3] = pk(p3.x, p3.y);
            }
            ldsm4(q0, sbB + boff[0][kk]);
            ldsm4(q1, sbB + boff[1][kk]);
            ldsm2(q2, sbB + boffc[kk]);
            mma_16x8x16(acc[0], afr, q0);
            mma_16x8x16(acc[1], afr, q0 + 2);
            mma_16x8x16(acc[2], afr, q1);
            mma_16x8x16(acc[3], afr, q1 + 2);
            mma_16x8x16(acc[4], afr, q2);
        }
    }
    __syncthreads();   // last stage consumed everywhere before overlay writes

    // ---- epilogue: prefetch chain weights into regs FIRST (overlaps writeback) ----
    float wreg[7];
    int   widx[7];
    #pragma unroll
    for (int k = 0; k < 7; ++k) {
        const int idx = tid + k * THREADS;
        widx[k] = idx;
        if (idx < 2 * Cc * Cc) {
            const int chn = idx / (Cc * Cc);
            const int rem = idx - chn * Cc * Cc;
            const int i = rem / Cc, j = rem - i * Cc;
            const float* Wp = chn ? Wr : W;
            wreg[k] = Wp[(size_t)i * (Dd + Cc) + Dd + j];
        }
    }
    float breg = 0.f;
    if (tid < 2 * Cc) breg = (tid < Cc) ? b[tid] : br[tid - Cc];

    // ---- accumulators -> smem bases[128][81] ----
    float* bases = smf + EPI_BASE_F;
    {
        const int r = mw * 16 + qr;
        #pragma unroll
        for (int t = 0; t < 5; ++t) {
            const int c = nw * 40 + t * 8 + qc * 2;
            bases[(r    ) * BROW + c    ] = acc[t][0];
            bases[(r    ) * BROW + c + 1] = acc[t][1];
            bases[(r + 8) * BROW + c    ] = acc[t][2];
            bases[(r + 8) * BROW + c + 1] = acc[t][3];
        }
    }

    float* wt = smf + EPI_WT_F;
    float* bb = smf + EPI_BB_F;
    #pragma unroll
    for (int k = 0; k < 7; ++k)
        if (widx[k] < 2 * Cc * Cc) wt[widx[k]] = wreg[k];
    if (tid < 2 * Cc) bb[tid] = breg;
    __syncthreads();

    // ---- sequential chains: threads 0..255 = 128 rows x 2 chains (split partials) ----
    if (tid < 256) {
        const int row = tid >> 1, chn = tid & 1;
        float* my        = bases + row * BROW + chn * Cc;
        const float* wtc = wt + chn * Cc * Cc;
        const float* bbc = bb + chn * Cc;
        float s[Cc];
        #pragma unroll
        for (int i = 0; i < Cc; ++i) {
            float x0 = my[i] + bbc[i];
            float x1 = 0.f;
            #pragma unroll
            for (int j = 0; j + 1 < i; j += 2) {
                x0 = fmaf(s[j],     wtc[i * Cc + j],     x0);
                x1 = fmaf(s[j + 1], wtc[i * Cc + j + 1], x1);
            }
            if (i & 1) x0 = fmaf(s[i - 1], wtc[i * Cc + i - 1], x0);
            const float x = x0 + x1;
            s[i] = 1.0f / (1.0f + __expf(-x));
            my[i] = s[i];
        }
    }
    __syncthreads();

    // ---- combine fwd + reversed rev, coalesced store ----
    #pragma unroll
    for (int it = 0; it < (RB * Cc) / THREADS; ++it) {   // 10
        const int idx = tid + it * THREADS;
        const int r = idx / Cc, c = idx - r * Cc;
        const float vf = bases[r * BROW + c];
        const float vr = bases[r * BROW + Cc + (Cc - 1 - c)];
        out[(size_t)(row0 + r) * Cc + c] = 0.5f * (vf + vr);
    }
}

extern "C" void kernel_launch(void* const* d_in, const int* in_sizes, int n_in,
                              void* d_out, int out_size) {
    const float* src = (const float*)d_in[0];
    // d_in[1] = attn_mask (unused)
    const float* W   = (const float*)d_in[2];
    const float* b   = (const float*)d_in[3];
    const float* Wr  = (const float*)d_in[4];
    const float* br  = (const float*)d_in[5];
    float* out = (float*)d_out;

    convert_w<<<(CT * Dd + 255) / 256, 256>>>(W, Wr);
    cudaFuncSetAttribute(bichain_w16,
                         cudaFuncAttributeMaxDynamicSharedMemorySize, SMEM_BYTES);
    bichain_w16<<<Bsz / RB, THREADS, SMEM_BYTES>>>(src, W, b, Wr, br, out);
}